// round 12
// baseline (speedup 1.0000x reference)
#include <cuda_runtime.h>
#include <cuda_fp16.h>
#include <math.h>
#include <stdint.h>

#define NTOK  32768
#define NCODE 8192
#define DIM   256
#define EPSF  1e-8f

#define BM 128
#define BN 256                   // block n-tile (4 wn x 64)
#define BK 16                    // K halfs per stage
#define KSTG 16                  // stages per n-block
#define THREADS 256

// persistent work decomposition: unit = (m-tile, n-quarter of 2048 codes)
#define NQ 4
#define UNIT_NBLK (NCODE / BN / NQ)          // 8 n-blocks per unit
#define UNIT_STAGES (UNIT_NBLK * KSTG)       // 128
#define UNITS ((NTOK / BM) * NQ)             // 1024
#define GRID  296

// smem geometry (bytes)
#define A_STRIDE 528             // 132 words: conflict-free ldmatrix
#define SM_B     (BM * A_STRIDE)             // 67584
#define BW_BUF   2048                        // 64 rows x 32B, XOR-swizzled
#define SM_BCAST (SM_B + 8 * 2 * BW_BUF)     // 100352
#define SM_TOTAL (SM_BCAST + 16)             // -> 2 CTA/SM

// ---- scratch (no allocations allowed) ----
__device__ __half g_ch[NCODE * DIM];
__device__ float  g_cnorm[NCODE];
__device__ unsigned long long g_best[NTOK];  // packed (ordered-dist, idx)
__device__ int    g_counts[NCODE];
__device__ int    g_unit_ctr;

__device__ __forceinline__ uint32_t smem_u32(const void* p) {
    uint32_t a;
    asm("{ .reg .u64 t; cvta.to.shared.u64 t, %1; cvt.u32.u64 %0, t; }"
        : "=r"(a) : "l"(p));
    return a;
}
__device__ __forceinline__ unsigned int f2ord(float f) {
    unsigned int u = __float_as_uint(f);
    return (u & 0x80000000u) ? ~u : (u | 0x80000000u);
}
#define CP_ASYNC16(dst, src) \
    asm volatile("cp.async.cg.shared.global [%0], [%1], 16;" :: "r"(dst), "l"(src))
#define CP_COMMIT() asm volatile("cp.async.commit_group;" ::: "memory")
#define CP_WAIT(n)  asm volatile("cp.async.wait_group %0;" :: "n"(n) : "memory")

#define LDSM_X4(r0, r1, r2, r3, addr) \
    asm volatile("ldmatrix.sync.aligned.m8n8.x4.shared.b16 {%0,%1,%2,%3}, [%4];" \
        : "=r"(r0), "=r"(r1), "=r"(r2), "=r"(r3) : "r"(addr))

// fp16-accumulator HMMA
__device__ __forceinline__ void mma_f16acc(uint32_t& c0, uint32_t& c1,
                                           uint32_t a0, uint32_t a1, uint32_t a2, uint32_t a3,
                                           uint32_t b0, uint32_t b1) {
    asm volatile(
        "mma.sync.aligned.m16n8k16.row.col.f16.f16.f16.f16 "
        "{%0,%1}, {%2,%3,%4,%5}, {%6,%7}, {%0,%1};"
        : "+r"(c0), "+r"(c1)
        : "r"(a0), "r"(a1), "r"(a2), "r"(a3), "r"(b0), "r"(b1));
}

// ---------------------------------------------------------------------------
// prep: C -> fp16, cnorm, zero counts, init g_best, reset unit counter
// ---------------------------------------------------------------------------
__global__ void prep_kernel(const float* __restrict__ C) {
    int gt = blockIdx.x * blockDim.x + threadIdx.x;
    if (gt < NTOK) g_best[gt] = ~0ull;
    if (gt == 0) g_unit_ctr = 0;
    int row  = gt >> 5;
    int lane = gt & 31;
    if (row >= NCODE) return;
    const float4* src = (const float4*)(C + (size_t)row * DIM) + lane * 2;
    float4 v0 = src[0], v1 = src[1];
    float s = v0.x * v0.x + v0.y * v0.y + v0.z * v0.z + v0.w * v0.w
            + v1.x * v1.x + v1.y * v1.y + v1.z * v1.z + v1.w * v1.w;
    __half2 h[4] = { __floats2half2_rn(v0.x, v0.y), __floats2half2_rn(v0.z, v0.w),
                     __floats2half2_rn(v1.x, v1.y), __floats2half2_rn(v1.z, v1.w) };
    *(uint4*)(g_ch + (size_t)row * DIM + lane * 8) = *(uint4*)h;
#pragma unroll
    for (int o = 16; o; o >>= 1) s += __shfl_xor_sync(0xffffffffu, s, o);
    if (lane == 0) { g_cnorm[row] = s; g_counts[row] = 0; }
}

// ---------------------------------------------------------------------------
// Persistent barrier-free fp16 mma.sync argmin GEMM.
// Warp tile 64m x 64n (mt=4, nt=8), BK=16, fp16 accumulators.
// A resident in smem; per-warp private XOR-swizzled B slices (64n x 16k),
// cp.async double-buffered. No __syncthreads in the main loop.
// ---------------------------------------------------------------------------
__global__ __launch_bounds__(THREADS, 2)
void argmin_mma_kernel(const float* __restrict__ X) {
    extern __shared__ __align__(16) char smem[];
    int* s_unit = (int*)(smem + SM_BCAST);

    const int tid  = threadIdx.x;
    const int lane = tid & 31;
    const int wid  = tid >> 5;
    const int wm   = wid >> 2;          // 0..1
    const int wn   = wid & 3;           // 0..3
    const int lr   = lane >> 2;
    const int lk   = lane & 3;

    const uint32_t sA  = smem_u32(smem);
    const uint32_t sBW = sA + SM_B + wid * (2 * BW_BUF);

    // A ldmatrix lane base (row-major A, padded stride)
    const uint32_t aBase = sA + (uint32_t)(wm * 64 + (lane & 15)) * A_STRIDE
                              + ((lane >> 4) & 1) * 16;

    // B ldmatrix lane offsets (XOR-swizzled, stride 32B, no padding)
    // rows rB + 16p, chunk qB; phys chunk = grp*8 + ((2*(r&3)+q) ^ (grp&7))
    const int rB = ((lane >> 4) & 1) * 8 + (lane & 7);
    const int qB = (lane >> 3) & 1;
    {
    }
    const int eL = ((rB & 3) << 1) | qB;
    const int gL = rB >> 2;                       // 0..3
    const uint32_t bL0 = (uint32_t)(gL * 128 + ((eL ^ gL) << 4));
    const uint32_t bL1 = bL0 + (((eL ^ gL) & 4) ? (512 - 64) : (512 + 64));

    // B staging lane offsets (same swizzle): rows rS + 16i, chunk qS
    const int rS = lane & 15;
    const int qS = lane >> 4;
    const int eS = ((rS & 3) << 1) | qS;
    const int gS = rS >> 2;
    const uint32_t dS0 = (uint32_t)(gS * 128 + ((eS ^ gS) << 4));
    const uint32_t dS1 = dS0 + (((eS ^ gS) & 4) ? (512 - 64) : (512 + 64));
    const int srcOff = rS * DIM + qS * 8;         // halfs

    int prev_m = -1;

    for (;;) {
        if (tid == 0) *s_unit = atomicAdd(&g_unit_ctr, 1);
        __syncthreads();
        const int u = *s_unit;
        __syncthreads();
        if (u >= UNITS) break;

        const int mi = u >> 2;      // m-tile
        const int nc = u & 3;       // n-quarter
        const int m0 = mi * BM;

        if (mi != prev_m) {
            // in-kernel A convert (fp32 X -> fp16 resident smem)
            const float4* xa = (const float4*)(X + (size_t)m0 * DIM);
#pragma unroll
            for (int r = 0; r < 16; r++) {
                int c   = tid + r * THREADS;
                int row = c >> 5, q = c & 31;
                float4 v0 = xa[row * 64 + q * 2];
                float4 v1 = xa[row * 64 + q * 2 + 1];
                __half2 h[4] = { __floats2half2_rn(v0.x, v0.y), __floats2half2_rn(v0.z, v0.w),
                                 __floats2half2_rn(v1.x, v1.y), __floats2half2_rn(v1.z, v1.w) };
                *(uint4*)(smem + row * A_STRIDE + q * 16) = *(uint4*)h;
            }
            __syncthreads();        // publish A
            prev_m = mi;
        }

        // warp's B source: 64 n-rows starting at nc*2048 + wn*64
        const __half* bSrcBase = g_ch + (size_t)(nc * 2048 + wn * 64) * DIM;

        // stage B(0) into buffer 0 (private; previous unit drained)
        {
            const __half* src = bSrcBase + srcOff;
            CP_ASYNC16(sBW + dS0,        src);
            CP_ASYNC16(sBW + dS1,        src + 16 * DIM);
            CP_ASYNC16(sBW + dS0 + 1024, src + 32 * DIM);
            CP_ASYNC16(sBW + dS1 + 1024, src + 48 * DIM);
        }
        CP_COMMIT();

        float bestd[8];
        int   besti[8];
#pragma unroll
        for (int i = 0; i < 8; i++) { bestd[i] = __int_as_float(0x7f800000); besti[i] = 0; }

        uint32_t acc[4][8][2];      // fp16x2 accumulators

        for (int s = 0; s < UNIT_STAGES; s++) {
            if (s + 1 < UNIT_STAGES) {
                const int t1 = (s + 1) >> 4, k1 = (s + 1) & 15;
                const uint32_t d = sBW + ((s + 1) & 1) * BW_BUF;
                const __half* src = bSrcBase + (size_t)t1 * BN * DIM + k1 * BK + srcOff;
                CP_ASYNC16(d + dS0,        src);
                CP_ASYNC16(d + dS1,        src + 16 * DIM);
                CP_ASYNC16(d + dS0 + 1024, src + 32 * DIM);
                CP_ASYNC16(d + dS1 + 1024, src + 48 * DIM);
                CP_COMMIT();
                CP_WAIT(1);
            } else {
                CP_WAIT(0);         // drain before next unit
            }

            const int ks = s & 15;
            const uint32_t aK = aBase + ks * 32;
            const uint32_t bK = sBW + (s & 1) * BW_BUF;

            if (ks == 0) {
#pragma unroll
                for (int mt = 0; mt < 4; mt++)
#pragma unroll
                    for (int nt = 0; nt < 8; nt++) {
                        acc[mt][nt][0] = 0u; acc[mt][nt][1] = 0u;
                    }
            }

            uint32_t af[4][4];
#pragma unroll
            for (int mt = 0; mt < 4; mt++)
                LDSM_X4(af[mt][0], af[mt][1], af[mt][2], af[mt][3],
                        aK + mt * (16 * A_STRIDE));
            uint32_t bf[8][2];
            LDSM_X4(bf[0][0], bf[0][1], bf[1][0], bf[1][1], bK + bL0);
            LDSM_X4(bf[2][0], bf[2][1], bf[3][0], bf[3][1], bK + bL1);
            LDSM_X4(bf[4][0], bf[4][1], bf[5][0], bf[5][1], bK + bL0 + 1024);
            LDSM_X4(bf[6][0], bf[6][1], bf[7][0], bf[7][1], bK + bL1 + 1024);

#pragma unroll
            for (int mt = 0; mt < 4; mt++)
#pragma unroll
                for (int nt = 0; nt < 8; nt++)
                    mma_f16acc(acc[mt][nt][0], acc[mt][nt][1],
                               af[mt][0], af[mt][1], af[mt][2], af[mt][3],
                               bf[nt][0], bf[nt][1]);

            if (ks == 15) {
                const int n0 = nc * 2048 + (s >> 4) * BN + wn * 64;
#pragma unroll
                for (int nt = 0; nt < 8; nt++) {
                    int col = n0 + nt * 8 + 2 * lk;
                    float cn0 = __ldg(&g_cnorm[col]);
                    float cn1 = __ldg(&g_cnorm[col + 1]);
#pragma unroll
                    for (int mt = 0; mt < 4; mt++) {
#pragma unroll
                        for (int h = 0; h < 2; h++) {
                            int bi = mt * 2 + h;
                            float2 dv = __half22float2(*(__half2*)&acc[mt][nt][h]);
                            float d0 = fmaf(-2.f, dv.x, cn0);
                            float d1 = fmaf(-2.f, dv.y, cn1);
                            if (d0 < bestd[bi]) { bestd[bi] = d0; besti[bi] = col; }
                            if (d1 < bestd[bi]) { bestd[bi] = d1; besti[bi] = col + 1; }
                        }
                    }
                }
            }
        }

        // flush unit results: reduce over lk (4 lanes) then atomicMin
#pragma unroll
        for (int mt = 0; mt < 4; mt++)
#pragma unroll
            for (int h = 0; h < 2; h++) {
                int bi = mt * 2 + h;
                unsigned long long p =
                    ((unsigned long long)f2ord(bestd[bi]) << 32) | (unsigned int)besti[bi];
                p = min(p, __shfl_xor_sync(0xffffffffu, p, 1));
                p = min(p, __shfl_xor_sync(0xffffffffu, p, 2));
                if (lk == 0)
                    atomicMin(&g_best[m0 + wm * 64 + mt * 16 + h * 8 + lr], p);
            }
    }
}

// ---------------------------------------------------------------------------
__global__ void epilogue_kernel(const float* __restrict__ X,
                                const float* __restrict__ R,
                                const float* __restrict__ C,
                                float* __restrict__ out) {
    int warp = (blockIdx.x * blockDim.x + threadIdx.x) >> 5;
    int lane = threadIdx.x & 31;
    if (warp >= NTOK) return;

    int idx = (int)(g_best[warp] & 0xffffffffu);
    if (lane == 0) atomicAdd(&g_counts[idx], 1);

    const float4* xr = (const float4*)(X + (size_t)warp * DIM);
    const float4* rr = (const float4*)(R + (size_t)warp * DIM);
    const float4* cr = (const float4*)(C + (size_t)idx * DIM);

    float4 xs[2], rs[2];
    float r2 = 0.f, n2 = 0.f;
#pragma unroll
    for (int i = 0; i < 2; i++) {
        float4 x = xr[lane + 32 * i];
        float4 c = cr[lane + 32 * i];
        float4 r = rr[lane + 32 * i];
        xs[i] = x; rs[i] = r;
        float dx = x.x - c.x, dy = x.y - c.y, dz = x.z - c.z, dw = x.w - c.w;
        r2 += dx * dx + dy * dy + dz * dz + dw * dw;
        n2 += r.x * r.x + r.y * r.y + r.z * r.z + r.w * r.w;
    }
#pragma unroll
    for (int o = 16; o; o >>= 1) {
        r2 += __shfl_xor_sync(0xffffffffu, r2, o);
        n2 += __shfl_xor_sync(0xffffffffu, n2, o);
    }
    float scale = sqrtf(r2) / (sqrtf(n2) + EPSF);

    float4* orow = (float4*)(out + (size_t)warp * DIM);
#pragma unroll
    for (int i = 0; i < 2; i++) {
        float4 x = xs[i], r = rs[i], o4;
        o4.x = fmaf(scale, r.x, x.x);
        o4.y = fmaf(scale, r.y, x.y);
        o4.z = fmaf(scale, r.z, x.z);
        o4.w = fmaf(scale, r.w, x.w);
        orow[lane + 32 * i] = o4;
    }
}

// ---------------------------------------------------------------------------
__global__ void finalize_kernel(float* __restrict__ out, int out_size) {
    __shared__ float s_ent[32];
    __shared__ int   s_uni[32];
    int tid = threadIdx.x;

    float ent = 0.f;
    int   uni = 0;
    for (int i = tid; i < NCODE; i += blockDim.x) {
        int c = g_counts[i];
        if (c > 0) {
            uni++;
            float p = (float)c * (1.0f / (float)NTOK);
            ent += p * logf(p + EPSF);
        }
    }
#pragma unroll
    for (int o = 16; o; o >>= 1) {
        ent += __shfl_xor_sync(0xffffffffu, ent, o);
        uni += __shfl_xor_sync(0xffffffffu, uni, o);
    }
    int warp = tid >> 5, lane = tid & 31;
    if (lane == 0) { s_ent[warp] = ent; s_uni[warp] = uni; }
    __syncthreads();
    if (warp == 0) {
        int nw = (blockDim.x + 31) >> 5;
        ent = (lane < nw) ? s_ent[lane] : 0.f;
        uni = (lane < nw) ? s_uni[lane] : 0;
#pragma unroll
        for (int o = 16; o; o >>= 1) {
            ent += __shfl_xor_sync(0xffffffffu, ent, o);
            uni += __shfl_xor_sync(0xffffffffu, uni, o);
        }
        if (lane == 0) {
            long long base = (long long)NTOK * DIM;
            if (out_size > base)     out[base]     = expf(-ent);
            if (out_size > base + 1) out[base + 1] = (float)uni;
        }
    }
}

// ---------------------------------------------------------------------------
extern "C" void kernel_launch(void* const* d_in, const int* in_sizes, int n_in,
                              void* d_out, int out_size) {
    const float* X = (const float*)d_in[0];
    const float* R = (const float*)d_in[1];
    const float* C = (const float*)d_in[2];
    float* out = (float*)d_out;

    cudaFuncSetAttribute(argmin_mma_kernel,
                         cudaFuncAttributeMaxDynamicSharedMemorySize, SM_TOTAL);

    prep_kernel<<<NCODE / 8, 256>>>(C);
    argmin_mma_kernel<<<GRID, THREADS, SM_TOTAL>>>(X);
    epilogue_kernel<<<(NTOK * 32) / 256, 256>>>(X, R, C, out);
    finalize_kernel<<<1, 1024>>>(out, out_size);
}

// round 13
// speedup vs baseline: 1.0274x; 1.0274x over previous
#include <cuda_runtime.h>
#include <cuda_fp16.h>
#include <math.h>
#include <stdint.h>

#define NTOK  32768
#define NCODE 8192
#define DIM   256
#define EPSF  1e-8f

#define BM 128
#define BN 128
#define BK 32                    // K halfs per stage (per-warp private B chunk)
#define KSTG  (DIM / BK)         // 8 stages per tile
#define THREADS 256

// persistent work decomposition: unit = (m-tile, n-eighth of 1024 codes)
#define NQ 8
#define UNIT_NTILES (NCODE / BN / NQ)        // 8 tiles per unit
#define UNIT_STAGES (UNIT_NTILES * KSTG)     // 64
#define UNITS ((NTOK / BM) * NQ)             // 2048
#define GRID  296

// smem geometry (bytes)
#define A_STRIDE 528             // 132 words (== 4 mod 32): conflict-free ldmatrix
#define B_STRIDE 80              // 20 words: 20r mod 32 distinct over r=0..7
#define SM_B     (BM * A_STRIDE)             // 67584
#define BW_BUF   (32 * B_STRIDE)             // 2560 per warp-buffer
#define SM_BCAST (SM_B + 8 * 2 * BW_BUF)     // 108544
#define SM_TOTAL (SM_BCAST + 16)             // 108560 -> 2 CTA/SM

// ---- scratch (no allocations allowed) ----
__device__ __half g_ch[NCODE * DIM];
__device__ float  g_cnorm[NCODE];
__device__ unsigned long long g_best[NTOK];  // packed (ordered-dist, idx)
__device__ int    g_counts[NCODE];
__device__ int    g_unit_ctr;

__device__ __forceinline__ uint32_t smem_u32(const void* p) {
    uint32_t a;
    asm("{ .reg .u64 t; cvta.to.shared.u64 t, %1; cvt.u32.u64 %0, t; }"
        : "=r"(a) : "l"(p));
    return a;
}
__device__ __forceinline__ unsigned int f2ord(float f) {
    unsigned int u = __float_as_uint(f);
    return (u & 0x80000000u) ? ~u : (u | 0x80000000u);
}
#define CP_ASYNC16(dst, src) \
    asm volatile("cp.async.cg.shared.global [%0], [%1], 16;" :: "r"(dst), "l"(src))
#define CP_COMMIT() asm volatile("cp.async.commit_group;" ::: "memory")
#define CP_WAIT(n)  asm volatile("cp.async.wait_group %0;" :: "n"(n) : "memory")

#define LDSM_X4(r0, r1, r2, r3, addr) \
    asm volatile("ldmatrix.sync.aligned.m8n8.x4.shared.b16 {%0,%1,%2,%3}, [%4];" \
        : "=r"(r0), "=r"(r1), "=r"(r2), "=r"(r3) : "r"(addr))

__device__ __forceinline__ void mma_f16(float& c0, float& c1, float& c2, float& c3,
                                        uint32_t a0, uint32_t a1, uint32_t a2, uint32_t a3,
                                        uint32_t b0, uint32_t b1) {
    asm volatile(
        "mma.sync.aligned.m16n8k16.row.col.f32.f16.f16.f32 "
        "{%0,%1,%2,%3}, {%4,%5,%6,%7}, {%8,%9}, {%0,%1,%2,%3};"
        : "+f"(c0), "+f"(c1), "+f"(c2), "+f"(c3)
        : "r"(a0), "r"(a1), "r"(a2), "r"(a3), "r"(b0), "r"(b1));
}

// ---------------------------------------------------------------------------
// prep: C -> fp16, cnorm, zero counts, init g_best, reset unit counter
// ---------------------------------------------------------------------------
__global__ void prep_kernel(const float* __restrict__ C) {
    int gt = blockIdx.x * blockDim.x + threadIdx.x;
    if (gt < NTOK) g_best[gt] = ~0ull;
    if (gt == 0) g_unit_ctr = 0;
    int row  = gt >> 5;
    int lane = gt & 31;
    if (row >= NCODE) return;
    const float4* src = (const float4*)(C + (size_t)row * DIM) + lane * 2;
    float4 v0 = src[0], v1 = src[1];
    float s = v0.x * v0.x + v0.y * v0.y + v0.z * v0.z + v0.w * v0.w
            + v1.x * v1.x + v1.y * v1.y + v1.z * v1.z + v1.w * v1.w;
    __half2 h[4] = { __floats2half2_rn(v0.x, v0.y), __floats2half2_rn(v0.z, v0.w),
                     __floats2half2_rn(v1.x, v1.y), __floats2half2_rn(v1.z, v1.w) };
    *(uint4*)(g_ch + (size_t)row * DIM + lane * 8) = *(uint4*)h;
#pragma unroll
    for (int o = 16; o; o >>= 1) s += __shfl_xor_sync(0xffffffffu, s, o);
    if (lane == 0) { g_cnorm[row] = s; g_counts[row] = 0; }
}

// ---------------------------------------------------------------------------
// Persistent barrier-free fp16 mma.sync argmin GEMM (R11 mainloop, NQ=8).
// Work units pulled from a global queue; A re-staged only on m-tile change;
// per-unit results merged via packed-u64 atomicMin.
// ---------------------------------------------------------------------------
__global__ __launch_bounds__(THREADS, 2)
void argmin_mma_kernel(const float* __restrict__ X) {
    extern __shared__ __align__(16) char smem[];
    int* s_unit = (int*)(smem + SM_BCAST);

    const int tid  = threadIdx.x;
    const int lane = tid & 31;
    const int wid  = tid >> 5;
    const int wm   = wid >> 2;          // 0..1
    const int wn   = wid & 3;           // 0..3
    const int lr   = lane >> 2;
    const int lk   = lane & 3;

    const uint32_t sA  = smem_u32(smem);
    const uint32_t sBW = sA + SM_B + wid * (2 * BW_BUF);

    const uint32_t aBase = sA + (uint32_t)(wm * 64 + (lane & 15)) * A_STRIDE
                              + ((lane >> 4) & 1) * 16;
    const uint32_t bFragOff = (uint32_t)(((lane >> 4) & 1) * 8 + (lane & 7)) * B_STRIDE
                              + ((lane >> 3) & 1) * 16;
    const int bRow0 = lane >> 2;
    const int bQ    = lane & 3;

    int prev_m = -1;

    for (;;) {
        if (tid == 0) *s_unit = atomicAdd(&g_unit_ctr, 1);
        __syncthreads();
        const int u = *s_unit;
        __syncthreads();            // allow tid0's next write; order A/B hazards
        if (u >= UNITS) break;

        const int mi = u >> 3;      // m-tile
        const int nc = u & 7;       // n-eighth
        const int m0 = mi * BM;

        if (mi != prev_m) {
            // in-kernel A convert (fp32 X -> fp16 resident smem)
            const float4* xa = (const float4*)(X + (size_t)m0 * DIM);
#pragma unroll
            for (int r = 0; r < 16; r++) {
                int c   = tid + r * THREADS;
                int row = c >> 5, q = c & 31;
                float4 v0 = xa[row * 64 + q * 2];
                float4 v1 = xa[row * 64 + q * 2 + 1];
                __half2 h[4] = { __floats2half2_rn(v0.x, v0.y), __floats2half2_rn(v0.z, v0.w),
                                 __floats2half2_rn(v1.x, v1.y), __floats2half2_rn(v1.z, v1.w) };
                *(uint4*)(smem + row * A_STRIDE + q * 16) = *(uint4*)h;
            }
            __syncthreads();        // publish A
            prev_m = mi;
        }

        const __half* bSrcBase = g_ch + (size_t)(nc * (NCODE / NQ) + wn * 32) * DIM;

        // stage this warp's B(0) (private buffer — no barrier needed)
#pragma unroll
        for (int i = 0; i < 4; i++) {
            int row = bRow0 + 8 * i;
            CP_ASYNC16(sBW + row * B_STRIDE + bQ * 16,
                       bSrcBase + (size_t)row * DIM + bQ * 8);
        }
        CP_COMMIT();

        float bestd[8];
        int   besti[8];
#pragma unroll
        for (int i = 0; i < 8; i++) { bestd[i] = __int_as_float(0x7f800000); besti[i] = 0; }

        float acc[4][4][4];

        for (int s = 0; s < UNIT_STAGES; s++) {
            if (s + 1 < UNIT_STAGES) {
                const int t1 = (s + 1) >> 3, k1 = (s + 1) & 7;
                const uint32_t d = sBW + ((s + 1) & 1) * BW_BUF;
                const __half* src = bSrcBase + (size_t)t1 * BN * DIM + k1 * BK;
#pragma unroll
                for (int i = 0; i < 4; i++) {
                    int row = bRow0 + 8 * i;
                    CP_ASYNC16(d + row * B_STRIDE + bQ * 16, src + (size_t)row * DIM + bQ * 8);
                }
                CP_COMMIT();
                CP_WAIT(1);
            } else {
                CP_WAIT(0);         // drain before next unit
            }

            const int ks = s & 7;
            const uint32_t aK = aBase + ks * 64;
            const uint32_t bK = sBW + (s & 1) * BW_BUF + bFragOff;

            if (ks == 0) {
#pragma unroll
                for (int mt = 0; mt < 4; mt++)
#pragma unroll
                    for (int nt = 0; nt < 4; nt++)
#pragma unroll
                        for (int e = 0; e < 4; e++) acc[mt][nt][e] = 0.f;
            }

#pragma unroll
            for (int kk = 0; kk < 2; kk++) {
                uint32_t af[4][4];
#pragma unroll
                for (int mt = 0; mt < 4; mt++)
                    LDSM_X4(af[mt][0], af[mt][1], af[mt][2], af[mt][3],
                            aK + kk * 32 + mt * (16 * A_STRIDE));
                uint32_t bf[4][2];
#pragma unroll
                for (int p = 0; p < 2; p++)
                    LDSM_X4(bf[2 * p][0], bf[2 * p][1], bf[2 * p + 1][0], bf[2 * p + 1][1],
                            bK + kk * 32 + p * (16 * B_STRIDE));
#pragma unroll
                for (int mt = 0; mt < 4; mt++)
#pragma unroll
                    for (int nt = 0; nt < 4; nt++)
                        mma_f16(acc[mt][nt][0], acc[mt][nt][1],
                                acc[mt][nt][2], acc[mt][nt][3],
                                af[mt][0], af[mt][1], af[mt][2], af[mt][3],
                                bf[nt][0], bf[nt][1]);
            }

            if (ks == 7) {
                const int n0 = nc * (NCODE / NQ) + (s >> 3) * BN;
#pragma unroll
                for (int nt = 0; nt < 4; nt++) {
                    int col = n0 + wn * 32 + nt * 8 + 2 * lk;
                    float cn0 = __ldg(&g_cnorm[col]);
                    float cn1 = __ldg(&g_cnorm[col + 1]);
#pragma unroll
                    for (int mt = 0; mt < 4; mt++) {
#pragma unroll
                        for (int h = 0; h < 2; h++) {
                            int bi = mt * 2 + h;
                            float d0 = fmaf(-2.f, acc[mt][nt][2 * h], cn0);
                            float d1 = fmaf(-2.f, acc[mt][nt][2 * h + 1], cn1);
                            if (d0 < bestd[bi]) { bestd[bi] = d0; besti[bi] = col; }
                            if (d1 < bestd[bi]) { bestd[bi] = d1; besti[bi] = col + 1; }
                        }
                    }
                }
            }
        }

        // flush unit results: reduce over lk (4 lanes) then atomicMin
#pragma unroll
        for (int mt = 0; mt < 4; mt++)
#pragma unroll
            for (int h = 0; h < 2; h++) {
                int bi = mt * 2 + h;
                unsigned long long p =
                    ((unsigned long long)f2ord(bestd[bi]) << 32) | (unsigned int)besti[bi];
                p = min(p, __shfl_xor_sync(0xffffffffu, p, 1));
                p = min(p, __shfl_xor_sync(0xffffffffu, p, 2));
                if (lk == 0)
                    atomicMin(&g_best[m0 + wm * 64 + mt * 16 + h * 8 + lr], p);
            }
    }
}

// ---------------------------------------------------------------------------
__global__ void epilogue_kernel(const float* __restrict__ X,
                                const float* __restrict__ R,
                                const float* __restrict__ C,
                                float* __restrict__ out) {
    int warp = (blockIdx.x * blockDim.x + threadIdx.x) >> 5;
    int lane = threadIdx.x & 31;
    if (warp >= NTOK) return;

    int idx = (int)(g_best[warp] & 0xffffffffu);
    if (lane == 0) atomicAdd(&g_counts[idx], 1);

    const float4* xr = (const float4*)(X + (size_t)warp * DIM);
    const float4* rr = (const float4*)(R + (size_t)warp * DIM);
    const float4* cr = (const float4*)(C + (size_t)idx * DIM);

    float4 xs[2], rs[2];
    float r2 = 0.f, n2 = 0.f;
#pragma unroll
    for (int i = 0; i < 2; i++) {
        float4 x = xr[lane + 32 * i];
        float4 c = cr[lane + 32 * i];
        float4 r = rr[lane + 32 * i];
        xs[i] = x; rs[i] = r;
        float dx = x.x - c.x, dy = x.y - c.y, dz = x.z - c.z, dw = x.w - c.w;
        r2 += dx * dx + dy * dy + dz * dz + dw * dw;
        n2 += r.x * r.x + r.y * r.y + r.z * r.z + r.w * r.w;
    }
#pragma unroll
    for (int o = 16; o; o >>= 1) {
        r2 += __shfl_xor_sync(0xffffffffu, r2, o);
        n2 += __shfl_xor_sync(0xffffffffu, n2, o);
    }
    float scale = sqrtf(r2) / (sqrtf(n2) + EPSF);

    float4* orow = (float4*)(out + (size_t)warp * DIM);
#pragma unroll
    for (int i = 0; i < 2; i++) {
        float4 x = xs[i], r = rs[i], o4;
        o4.x = fmaf(scale, r.x, x.x);
        o4.y = fmaf(scale, r.y, x.y);
        o4.z = fmaf(scale, r.z, x.z);
        o4.w = fmaf(scale, r.w, x.w);
        orow[lane + 32 * i] = o4;
    }
}

// ---------------------------------------------------------------------------
__global__ void finalize_kernel(float* __restrict__ out, int out_size) {
    __shared__ float s_ent[32];
    __shared__ int   s_uni[32];
    int tid = threadIdx.x;

    float ent = 0.f;
    int   uni = 0;
    for (int i = tid; i < NCODE; i += blockDim.x) {
        int c = g_counts[i];
        if (c > 0) {
            uni++;
            float p = (float)c * (1.0f / (float)NTOK);
            ent += p * logf(p + EPSF);
        }
    }
#pragma unroll
    for (int o = 16; o; o >>= 1) {
        ent += __shfl_xor_sync(0xffffffffu, ent, o);
        uni += __shfl_xor_sync(0xffffffffu, uni, o);
    }
    int warp = tid >> 5, lane = tid & 31;
    if (lane == 0) { s_ent[warp] = ent; s_uni[warp] = uni; }
    __syncthreads();
    if (warp == 0) {
        int nw = (blockDim.x + 31) >> 5;
        ent = (lane < nw) ? s_ent[lane] : 0.f;
        uni = (lane < nw) ? s_uni[lane] : 0;
#pragma unroll
        for (int o = 16; o; o >>= 1) {
            ent += __shfl_xor_sync(0xffffffffu, ent, o);
            uni += __shfl_xor_sync(0xffffffffu, uni, o);
        }
        if (lane == 0) {
            long long base = (long long)NTOK * DIM;
            if (out_size > base)     out[base]     = expf(-ent);
            if (out_size > base + 1) out[base + 1] = (float)uni;
        }
    }
}

// ---------------------------------------------------------------------------
extern "C" void kernel_launch(void* const* d_in, const int* in_sizes, int n_in,
                              void* d_out, int out_size) {
    const float* X = (const float*)d_in[0];
    const float* R = (const float*)d_in[1];
    const float* C = (const float*)d_in[2];
    float* out = (float*)d_out;

    cudaFuncSetAttribute(argmin_mma_kernel,
                         cudaFuncAttributeMaxDynamicSharedMemorySize, SM_TOTAL);

    prep_kernel<<<NCODE / 8, 256>>>(C);
    argmin_mma_kernel<<<GRID, THREADS, SM_TOTAL>>>(X);
    epilogue_kernel<<<(NTOK * 32) / 256, 256>>>(X, R, C, out);
    finalize_kernel<<<1, 1024>>>(out, out_size);
}

// round 14
// speedup vs baseline: 1.0887x; 1.0597x over previous
#include <cuda_runtime.h>
#include <cuda_fp16.h>
#include <math.h>
#include <stdint.h>

#define NTOK  32768
#define NCODE 8192
#define DIM   256
#define EPSF  1e-8f

#define BM 128
#define BN 128
#define BK 32                    // K halfs per stage (per-pair shared B chunk)
#define KSTG  (DIM / BK)         // 8 stages per tile
#define THREADS 256

// persistent work decomposition: unit = (m-tile, n-quarter of 2048 codes)
#define NQ 4
#define UNIT_NTILES (NCODE / BN / NQ)        // 16 tiles per unit
#define UNIT_STAGES (UNIT_NTILES * KSTG)     // 128
#define UNITS ((NTOK / BM) * NQ)             // 1024
#define GRID  296

// smem geometry (bytes)
#define A_STRIDE 528             // 132 words (== 4 mod 32): conflict-free ldmatrix
#define B_STRIDE 80              // 20 words: 20r mod 32 distinct over r=0..7
#define SM_B     (BM * A_STRIDE)             // 67584
#define BW_BUF   (32 * B_STRIDE)             // 2560 per buffer
#define SM_BCAST (SM_B + 4 * 2 * BW_BUF)     // 88064 (4 wn-pairs x 2 buffers)
#define SM_TOTAL (SM_BCAST + 16)             // 88080 -> 2 CTA/SM

// ---- scratch (no allocations allowed) ----
__device__ __half g_ch[NCODE * DIM];
__device__ float  g_cnorm[NCODE];
__device__ unsigned long long g_best[NTOK];  // packed (ordered-dist, idx)
__device__ int    g_counts[NCODE];
__device__ int    g_unit_ctr;

__device__ __forceinline__ uint32_t smem_u32(const void* p) {
    uint32_t a;
    asm("{ .reg .u64 t; cvta.to.shared.u64 t, %1; cvt.u32.u64 %0, t; }"
        : "=r"(a) : "l"(p));
    return a;
}
__device__ __forceinline__ unsigned int f2ord(float f) {
    unsigned int u = __float_as_uint(f);
    return (u & 0x80000000u) ? ~u : (u | 0x80000000u);
}
#define CP_ASYNC16(dst, src) \
    asm volatile("cp.async.cg.shared.global [%0], [%1], 16;" :: "r"(dst), "l"(src))
#define CP_COMMIT() asm volatile("cp.async.commit_group;" ::: "memory")
#define CP_WAIT(n)  asm volatile("cp.async.wait_group %0;" :: "n"(n) : "memory")
#define PAIR_BAR(id) \
    asm volatile("bar.sync %0, 64;" :: "r"(id) : "memory")

#define LDSM_X4(r0, r1, r2, r3, addr) \
    asm volatile("ldmatrix.sync.aligned.m8n8.x4.shared.b16 {%0,%1,%2,%3}, [%4];" \
        : "=r"(r0), "=r"(r1), "=r"(r2), "=r"(r3) : "r"(addr))

__device__ __forceinline__ void mma_f16(float& c0, float& c1, float& c2, float& c3,
                                        uint32_t a0, uint32_t a1, uint32_t a2, uint32_t a3,
                                        uint32_t b0, uint32_t b1) {
    asm volatile(
        "mma.sync.aligned.m16n8k16.row.col.f32.f16.f16.f32 "
        "{%0,%1,%2,%3}, {%4,%5,%6,%7}, {%8,%9}, {%0,%1,%2,%3};"
        : "+f"(c0), "+f"(c1), "+f"(c2), "+f"(c3)
        : "r"(a0), "r"(a1), "r"(a2), "r"(a3), "r"(b0), "r"(b1));
}

// ---------------------------------------------------------------------------
// prep: C -> fp16, cnorm, zero counts, init g_best, reset unit counter
// ---------------------------------------------------------------------------
__global__ void prep_kernel(const float* __restrict__ C) {
    int gt = blockIdx.x * blockDim.x + threadIdx.x;
    if (gt < NTOK) g_best[gt] = ~0ull;
    if (gt == 0) g_unit_ctr = 0;
    int row  = gt >> 5;
    int lane = gt & 31;
    if (row >= NCODE) return;
    const float4* src = (const float4*)(C + (size_t)row * DIM) + lane * 2;
    float4 v0 = src[0], v1 = src[1];
    float s = v0.x * v0.x + v0.y * v0.y + v0.z * v0.z + v0.w * v0.w
            + v1.x * v1.x + v1.y * v1.y + v1.z * v1.z + v1.w * v1.w;
    __half2 h[4] = { __floats2half2_rn(v0.x, v0.y), __floats2half2_rn(v0.z, v0.w),
                     __floats2half2_rn(v1.x, v1.y), __floats2half2_rn(v1.z, v1.w) };
    *(uint4*)(g_ch + (size_t)row * DIM + lane * 8) = *(uint4*)h;
#pragma unroll
    for (int o = 16; o; o >>= 1) s += __shfl_xor_sync(0xffffffffu, s, o);
    if (lane == 0) { g_cnorm[row] = s; g_counts[row] = 0; }
}

// ---------------------------------------------------------------------------
// Persistent fp16 mma.sync argmin GEMM (R11 mainloop + pair-shared B).
// A resident in smem. B slices shared between the two warps with equal wn:
// only wm=0 stages via cp.async; the pair syncs with a 2-warp named barrier.
// ---------------------------------------------------------------------------
__global__ __launch_bounds__(THREADS, 2)
void argmin_mma_kernel(const float* __restrict__ X) {
    extern __shared__ __align__(16) char smem[];
    int* s_unit = (int*)(smem + SM_BCAST);

    const int tid  = threadIdx.x;
    const int lane = tid & 31;
    const int wid  = tid >> 5;
    const int wm   = wid >> 2;          // 0..1
    const int wn   = wid & 3;           // 0..3
    const int lr   = lane >> 2;
    const int lk   = lane & 3;

    const uint32_t sA  = smem_u32(smem);
    const uint32_t sBW = sA + SM_B + wn * (2 * BW_BUF);   // shared per wn-pair

    const uint32_t aBase = sA + (uint32_t)(wm * 64 + (lane & 15)) * A_STRIDE
                              + ((lane >> 4) & 1) * 16;
    const uint32_t bFragOff = (uint32_t)(((lane >> 4) & 1) * 8 + (lane & 7)) * B_STRIDE
                              + ((lane >> 3) & 1) * 16;
    const int bRow0 = lane >> 2;
    const int bQ    = lane & 3;
    const int barid = wn + 1;           // HW barriers 1..4 (0 = __syncthreads)

    int prev_m = -1;

    for (;;) {
        if (tid == 0) *s_unit = atomicAdd(&g_unit_ctr, 1);
        __syncthreads();
        const int u = *s_unit;
        __syncthreads();            // allow tid0's next write; order A/B hazards
        if (u >= UNITS) break;

        const int mi = u >> 2;      // m-tile
        const int nc = u & 3;       // n-quarter
        const int m0 = mi * BM;

        if (mi != prev_m) {
            // in-kernel A convert (fp32 X -> fp16 resident smem)
            const float4* xa = (const float4*)(X + (size_t)m0 * DIM);
#pragma unroll
            for (int r = 0; r < 16; r++) {
                int c   = tid + r * THREADS;
                int row = c >> 5, q = c & 31;
                float4 v0 = xa[row * 64 + q * 2];
                float4 v1 = xa[row * 64 + q * 2 + 1];
                __half2 h[4] = { __floats2half2_rn(v0.x, v0.y), __floats2half2_rn(v0.z, v0.w),
                                 __floats2half2_rn(v1.x, v1.y), __floats2half2_rn(v1.z, v1.w) };
                *(uint4*)(smem + row * A_STRIDE + q * 16) = *(uint4*)h;
            }
            __syncthreads();        // publish A
            prev_m = mi;
        }

        const __half* bSrcBase = g_ch + (size_t)(nc * (NCODE / NQ) + wn * 32) * DIM;

        // stage B(0): wm=0 warp only (shared buffer)
        if (wm == 0) {
#pragma unroll
            for (int i = 0; i < 4; i++) {
                int row = bRow0 + 8 * i;
                CP_ASYNC16(sBW + row * B_STRIDE + bQ * 16,
                           bSrcBase + (size_t)row * DIM + bQ * 8);
            }
            CP_COMMIT();
        }

        float bestd[8];
        int   besti[8];
#pragma unroll
        for (int i = 0; i < 8; i++) { bestd[i] = __int_as_float(0x7f800000); besti[i] = 0; }

        float acc[4][4][4];

        for (int s = 0; s < UNIT_STAGES; s++) {
            // a) staging warp drains the group for stage s (issued a stage ago)
            if (wm == 0) CP_WAIT(0);
            // b) pair barrier: publishes stage-s data to wm=1 AND confirms the
            //    pair finished reading buf[(s+1)&1] (its last read was stage s-1)
            PAIR_BAR(barid);
            // c) staging warp issues prefetch for stage s+1
            if (wm == 0 && s + 1 < UNIT_STAGES) {
                const int t1 = (s + 1) >> 3, k1 = (s + 1) & 7;
                const uint32_t d = sBW + ((s + 1) & 1) * BW_BUF;
                const __half* src = bSrcBase + (size_t)t1 * BN * DIM + k1 * BK;
#pragma unroll
                for (int i = 0; i < 4; i++) {
                    int row = bRow0 + 8 * i;
                    CP_ASYNC16(d + row * B_STRIDE + bQ * 16, src + (size_t)row * DIM + bQ * 8);
                }
                CP_COMMIT();
            }

            const int ks = s & 7;
            const uint32_t aK = aBase + ks * 64;
            const uint32_t bK = sBW + (s & 1) * BW_BUF + bFragOff;

            if (ks == 0) {
#pragma unroll
                for (int mt = 0; mt < 4; mt++)
#pragma unroll
                    for (int nt = 0; nt < 4; nt++)
#pragma unroll
                        for (int e = 0; e < 4; e++) acc[mt][nt][e] = 0.f;
            }

#pragma unroll
            for (int kk = 0; kk < 2; kk++) {
                uint32_t af[4][4];
#pragma unroll
                for (int mt = 0; mt < 4; mt++)
                    LDSM_X4(af[mt][0], af[mt][1], af[mt][2], af[mt][3],
                            aK + kk * 32 + mt * (16 * A_STRIDE));
                uint32_t bf[4][2];
#pragma unroll
                for (int p = 0; p < 2; p++)
                    LDSM_X4(bf[2 * p][0], bf[2 * p][1], bf[2 * p + 1][0], bf[2 * p + 1][1],
                            bK + kk * 32 + p * (16 * B_STRIDE));
#pragma unroll
                for (int mt = 0; mt < 4; mt++)
#pragma unroll
                    for (int nt = 0; nt < 4; nt++)
                        mma_f16(acc[mt][nt][0], acc[mt][nt][1],
                                acc[mt][nt][2], acc[mt][nt][3],
                                af[mt][0], af[mt][1], af[mt][2], af[mt][3],
                                bf[nt][0], bf[nt][1]);
            }

            if (ks == 7) {
                const int n0 = nc * (NCODE / NQ) + (s >> 3) * BN;
#pragma unroll
                for (int nt = 0; nt < 4; nt++) {
                    int col = n0 + wn * 32 + nt * 8 + 2 * lk;
                    float cn0 = __ldg(&g_cnorm[col]);
                    float cn1 = __ldg(&g_cnorm[col + 1]);
#pragma unroll
                    for (int mt = 0; mt < 4; mt++) {
#pragma unroll
                        for (int h = 0; h < 2; h++) {
                            int bi = mt * 2 + h;
                            float d0 = fmaf(-2.f, acc[mt][nt][2 * h], cn0);
                            float d1 = fmaf(-2.f, acc[mt][nt][2 * h + 1], cn1);
                            if (d0 < bestd[bi]) { bestd[bi] = d0; besti[bi] = col; }
                            if (d1 < bestd[bi]) { bestd[bi] = d1; besti[bi] = col + 1; }
                        }
                    }
                }
            }
        }

        // ensure the pair finished reading the last buffer before the next
        // unit's B(0) staging overwrites buffer 0
        PAIR_BAR(barid);

        // flush unit results: reduce over lk (4 lanes) then atomicMin
#pragma unroll
        for (int mt = 0; mt < 4; mt++)
#pragma unroll
            for (int h = 0; h < 2; h++) {
                int bi = mt * 2 + h;
                unsigned long long p =
                    ((unsigned long long)f2ord(bestd[bi]) << 32) | (unsigned int)besti[bi];
                p = min(p, __shfl_xor_sync(0xffffffffu, p, 1));
                p = min(p, __shfl_xor_sync(0xffffffffu, p, 2));
                if (lk == 0)
                    atomicMin(&g_best[m0 + wm * 64 + mt * 16 + h * 8 + lr], p);
            }
    }
}

// ---------------------------------------------------------------------------
__global__ void epilogue_kernel(const float* __restrict__ X,
                                const float* __restrict__ R,
                                const float* __restrict__ C,
                                float* __restrict__ out) {
    int warp = (blockIdx.x * blockDim.x + threadIdx.x) >> 5;
    int lane = threadIdx.x & 31;
    if (warp >= NTOK) return;

    int idx = (int)(g_best[warp] & 0xffffffffu);
    if (lane == 0) atomicAdd(&g_counts[idx], 1);

    const float4* xr = (const float4*)(X + (size_t)warp * DIM);
    const float4* rr = (const float4*)(R + (size_t)warp * DIM);
    const float4* cr = (const float4*)(C + (size_t)idx * DIM);

    float4 xs[2], rs[2];
    float r2 = 0.f, n2 = 0.f;
#pragma unroll
    for (int i = 0; i < 2; i++) {
        float4 x = xr[lane + 32 * i];
        float4 c = cr[lane + 32 * i];
        float4 r = rr[lane + 32 * i];
        xs[i] = x; rs[i] = r;
        float dx = x.x - c.x, dy = x.y - c.y, dz = x.z - c.z, dw = x.w - c.w;
        r2 += dx * dx + dy * dy + dz * dz + dw * dw;
        n2 += r.x * r.x + r.y * r.y + r.z * r.z + r.w * r.w;
    }
#pragma unroll
    for (int o = 16; o; o >>= 1) {
        r2 += __shfl_xor_sync(0xffffffffu, r2, o);
        n2 += __shfl_xor_sync(0xffffffffu, n2, o);
    }
    float scale = sqrtf(r2) / (sqrtf(n2) + EPSF);

    float4* orow = (float4*)(out + (size_t)warp * DIM);
#pragma unroll
    for (int i = 0; i < 2; i++) {
        float4 x = xs[i], r = rs[i], o4;
        o4.x = fmaf(scale, r.x, x.x);
        o4.y = fmaf(scale, r.y, x.y);
        o4.z = fmaf(scale, r.z, x.z);
        o4.w = fmaf(scale, r.w, x.w);
        orow[lane + 32 * i] = o4;
    }
}

// ---------------------------------------------------------------------------
__global__ void finalize_kernel(float* __restrict__ out, int out_size) {
    __shared__ float s_ent[32];
    __shared__ int   s_uni[32];
    int tid = threadIdx.x;

    float ent = 0.f;
    int   uni = 0;
    for (int i = tid; i < NCODE; i += blockDim.x) {
        int c = g_counts[i];
        if (c > 0) {
            uni++;
            float p = (float)c * (1.0f / (float)NTOK);
            ent += p * logf(p + EPSF);
        }
    }
#pragma unroll
    for (int o = 16; o; o >>= 1) {
        ent += __shfl_xor_sync(0xffffffffu, ent, o);
        uni += __shfl_xor_sync(0xffffffffu, uni, o);
    }
    int warp = tid >> 5, lane = tid & 31;
    if (lane == 0) { s_ent[warp] = ent; s_uni[warp] = uni; }
    __syncthreads();
    if (warp == 0) {
        int nw = (blockDim.x + 31) >> 5;
        ent = (lane < nw) ? s_ent[lane] : 0.f;
        uni = (lane < nw) ? s_uni[lane] : 0;
#pragma unroll
        for (int o = 16; o; o >>= 1) {
            ent += __shfl_xor_sync(0xffffffffu, ent, o);
            uni += __shfl_xor_sync(0xffffffffu, uni, o);
        }
        if (lane == 0) {
            long long base = (long long)NTOK * DIM;
            if (out_size > base)     out[base]     = expf(-ent);
            if (out_size > base + 1) out[base + 1] = (float)uni;
        }
    }
}

// ---------------------------------------------------------------------------
extern "C" void kernel_launch(void* const* d_in, const int* in_sizes, int n_in,
                              void* d_out, int out_size) {
    const float* X = (const float*)d_in[0];
    const float* R = (const float*)d_in[1];
    const float* C = (const float*)d_in[2];
    float* out = (float*)d_out;

    cudaFuncSetAttribute(argmin_mma_kernel,
                         cudaFuncAttributeMaxDynamicSharedMemorySize, SM_TOTAL);

    prep_kernel<<<NCODE / 8, 256>>>(C);
    argmin_mma_kernel<<<GRID, THREADS, SM_TOTAL>>>(X);
    epilogue_kernel<<<(NTOK * 32) / 256, 256>>>(X, R, C, out);
    finalize_kernel<<<1, 1024>>>(out, out_size);
}

// round 15
// speedup vs baseline: 1.1296x; 1.0375x over previous
#include <cuda_runtime.h>
#include <cuda_fp16.h>
#include <math.h>
#include <stdint.h>

#define NTOK  32768
#define NCODE 8192
#define DIM   256
#define EPSF  1e-8f

#define BM 128
#define BN 128
#define BK 32                    // K halfs per stage (per-pair shared B chunk)
#define KSTG  (DIM / BK)         // 8 stages per tile
#define THREADS 256

// persistent work decomposition: unit = (m-tile, n-quarter of 2048 codes)
#define NQ 4
#define UNIT_NTILES (NCODE / BN / NQ)        // 16 tiles per unit
#define UNIT_STAGES (UNIT_NTILES * KSTG)     // 128
#define UNITS ((NTOK / BM) * NQ)             // 1024
#define GRID  296

// smem geometry (bytes)
#define A_STRIDE 528             // 132 words (== 4 mod 32): conflict-free ldmatrix
#define B_STRIDE 80              // 20 words: 20r mod 32 distinct over r=0..7
#define SM_B     (BM * A_STRIDE)             // 67584
#define BW_BUF   (32 * B_STRIDE)             // 2560 per buffer
#define SM_BCAST (SM_B + 4 * 4 * BW_BUF)     // 108544 (4 wn-pairs x 4 buffers)
#define SM_TOTAL (SM_BCAST + 16)             // 108560 -> 2 CTA/SM

// ---- scratch (no allocations allowed) ----
__device__ __half g_ch[NCODE * DIM];
__device__ float  g_cnorm[NCODE];
__device__ unsigned long long g_best[NTOK];  // packed (ordered-dist, idx)
__device__ int    g_counts[NCODE];
__device__ int    g_unit_ctr;

__device__ __forceinline__ uint32_t smem_u32(const void* p) {
    uint32_t a;
    asm("{ .reg .u64 t; cvta.to.shared.u64 t, %1; cvt.u32.u64 %0, t; }"
        : "=r"(a) : "l"(p));
    return a;
}
__device__ __forceinline__ unsigned int f2ord(float f) {
    unsigned int u = __float_as_uint(f);
    return (u & 0x80000000u) ? ~u : (u | 0x80000000u);
}
#define CP_ASYNC16(dst, src) \
    asm volatile("cp.async.cg.shared.global [%0], [%1], 16;" :: "r"(dst), "l"(src))
#define CP_COMMIT() asm volatile("cp.async.commit_group;" ::: "memory")
#define CP_WAIT(n)  asm volatile("cp.async.wait_group %0;" :: "n"(n) : "memory")
#define PAIR_BAR(id) \
    asm volatile("bar.sync %0, 64;" :: "r"(id) : "memory")

#define LDSM_X4(r0, r1, r2, r3, addr) \
    asm volatile("ldmatrix.sync.aligned.m8n8.x4.shared.b16 {%0,%1,%2,%3}, [%4];" \
        : "=r"(r0), "=r"(r1), "=r"(r2), "=r"(r3) : "r"(addr))

__device__ __forceinline__ void mma_f16(float& c0, float& c1, float& c2, float& c3,
                                        uint32_t a0, uint32_t a1, uint32_t a2, uint32_t a3,
                                        uint32_t b0, uint32_t b1) {
    asm volatile(
        "mma.sync.aligned.m16n8k16.row.col.f32.f16.f16.f32 "
        "{%0,%1,%2,%3}, {%4,%5,%6,%7}, {%8,%9}, {%0,%1,%2,%3};"
        : "+f"(c0), "+f"(c1), "+f"(c2), "+f"(c3)
        : "r"(a0), "r"(a1), "r"(a2), "r"(a3), "r"(b0), "r"(b1));
}

// ---------------------------------------------------------------------------
// prep: C -> fp16, cnorm, zero counts, init g_best, reset unit counter
// ---------------------------------------------------------------------------
__global__ void prep_kernel(const float* __restrict__ C) {
    int gt = blockIdx.x * blockDim.x + threadIdx.x;
    if (gt < NTOK) g_best[gt] = ~0ull;
    if (gt == 0) g_unit_ctr = 0;
    int row  = gt >> 5;
    int lane = gt & 31;
    if (row >= NCODE) return;
    const float4* src = (const float4*)(C + (size_t)row * DIM) + lane * 2;
    float4 v0 = src[0], v1 = src[1];
    float s = v0.x * v0.x + v0.y * v0.y + v0.z * v0.z + v0.w * v0.w
            + v1.x * v1.x + v1.y * v1.y + v1.z * v1.z + v1.w * v1.w;
    __half2 h[4] = { __floats2half2_rn(v0.x, v0.y), __floats2half2_rn(v0.z, v0.w),
                     __floats2half2_rn(v1.x, v1.y), __floats2half2_rn(v1.z, v1.w) };
    *(uint4*)(g_ch + (size_t)row * DIM + lane * 8) = *(uint4*)h;
#pragma unroll
    for (int o = 16; o; o >>= 1) s += __shfl_xor_sync(0xffffffffu, s, o);
    if (lane == 0) { g_cnorm[row] = s; g_counts[row] = 0; }
}

// ---------------------------------------------------------------------------
// Persistent fp16 mma.sync argmin GEMM: pair-shared QUAD-buffered B,
// one pair-barrier per 2 stages, prefetch distance 2.
// ---------------------------------------------------------------------------
__global__ __launch_bounds__(THREADS, 2)
void argmin_mma_kernel(const float* __restrict__ X) {
    extern __shared__ __align__(16) char smem[];
    int* s_unit = (int*)(smem + SM_BCAST);

    const int tid  = threadIdx.x;
    const int lane = tid & 31;
    const int wid  = tid >> 5;
    const int wm   = wid >> 2;          // 0..1
    const int wn   = wid & 3;           // 0..3
    const int lr   = lane >> 2;
    const int lk   = lane & 3;

    const uint32_t sA  = smem_u32(smem);
    const uint32_t sBW = sA + SM_B + wn * (4 * BW_BUF);   // shared per wn-pair

    const uint32_t aBase = sA + (uint32_t)(wm * 64 + (lane & 15)) * A_STRIDE
                              + ((lane >> 4) & 1) * 16;
    const uint32_t bFragOff = (uint32_t)(((lane >> 4) & 1) * 8 + (lane & 7)) * B_STRIDE
                              + ((lane >> 3) & 1) * 16;
    const int bRow0 = lane >> 2;
    const int bQ    = lane & 3;
    const int barid = wn + 1;           // HW barriers 1..4 (0 = __syncthreads)

    int prev_m = -1;

    for (;;) {
        if (tid == 0) *s_unit = atomicAdd(&g_unit_ctr, 1);
        __syncthreads();
        const int u = *s_unit;
        __syncthreads();            // allow tid0's next write; order A/B hazards
        if (u >= UNITS) break;

        const int mi = u >> 2;      // m-tile
        const int nc = u & 3;       // n-quarter
        const int m0 = mi * BM;

        if (mi != prev_m) {
            // in-kernel A convert (fp32 X -> fp16 resident smem)
            const float4* xa = (const float4*)(X + (size_t)m0 * DIM);
#pragma unroll
            for (int r = 0; r < 16; r++) {
                int c   = tid + r * THREADS;
                int row = c >> 5, q = c & 31;
                float4 v0 = xa[row * 64 + q * 2];
                float4 v1 = xa[row * 64 + q * 2 + 1];
                __half2 h[4] = { __floats2half2_rn(v0.x, v0.y), __floats2half2_rn(v0.z, v0.w),
                                 __floats2half2_rn(v1.x, v1.y), __floats2half2_rn(v1.z, v1.w) };
                *(uint4*)(smem + row * A_STRIDE + q * 16) = *(uint4*)h;
            }
            __syncthreads();        // publish A
            prev_m = mi;
        }

        const __half* bSrcBase = g_ch + (size_t)(nc * (NCODE / NQ) + wn * 32) * DIM;

        // stage B(0) and B(1) into buffers 0,1 (wm=0 only; shared buffers)
        if (wm == 0) {
#pragma unroll
            for (int s0 = 0; s0 < 2; s0++) {
                const uint32_t d = sBW + s0 * BW_BUF;
                const __half* src = bSrcBase + s0 * BK;
#pragma unroll
                for (int i = 0; i < 4; i++) {
                    int row = bRow0 + 8 * i;
                    CP_ASYNC16(d + row * B_STRIDE + bQ * 16,
                               src + (size_t)row * DIM + bQ * 8);
                }
            }
            CP_COMMIT();
        }

        float bestd[8];
        int   besti[8];
#pragma unroll
        for (int i = 0; i < 8; i++) { bestd[i] = __int_as_float(0x7f800000); besti[i] = 0; }

        float acc[4][4][4];

        for (int s = 0; s < UNIT_STAGES; s += 2) {
            // a) staging warp drains everything outstanding (stages s, s+1 ready)
            if (wm == 0) CP_WAIT(0);
            // b) pair barrier: publishes stages s,s+1 to wm=1 AND confirms the
            //    pair finished reading buffers (s+2)&3,(s+3)&3 (read 2 stages ago)
            PAIR_BAR(barid);
            // c) staging warp issues prefetch for stages s+2, s+3
            if (wm == 0 && s + 2 < UNIT_STAGES) {
#pragma unroll
                for (int pf = 0; pf < 2; pf++) {
                    const int sn = s + 2 + pf;
                    const int t1 = sn >> 3, k1 = sn & 7;
                    const uint32_t d = sBW + (sn & 3) * BW_BUF;
                    const __half* src = bSrcBase + (size_t)t1 * BN * DIM + k1 * BK;
#pragma unroll
                    for (int i = 0; i < 4; i++) {
                        int row = bRow0 + 8 * i;
                        CP_ASYNC16(d + row * B_STRIDE + bQ * 16,
                                   src + (size_t)row * DIM + bQ * 8);
                    }
                }
                CP_COMMIT();
            }

            // compute stages s and s+1
#pragma unroll
            for (int hh = 0; hh < 2; hh++) {
                const int sc = s + hh;
                const int ks = sc & 7;
                const uint32_t aK = aBase + ks * 64;
                const uint32_t bK = sBW + (sc & 3) * BW_BUF + bFragOff;

                if (ks == 0) {
#pragma unroll
                    for (int mt = 0; mt < 4; mt++)
#pragma unroll
                        for (int nt = 0; nt < 4; nt++)
#pragma unroll
                            for (int e = 0; e < 4; e++) acc[mt][nt][e] = 0.f;
                }

#pragma unroll
                for (int kk = 0; kk < 2; kk++) {
                    uint32_t af[4][4];
#pragma unroll
                    for (int mt = 0; mt < 4; mt++)
                        LDSM_X4(af[mt][0], af[mt][1], af[mt][2], af[mt][3],
                                aK + kk * 32 + mt * (16 * A_STRIDE));
                    uint32_t bf[4][2];
#pragma unroll
                    for (int p = 0; p < 2; p++)
                        LDSM_X4(bf[2 * p][0], bf[2 * p][1], bf[2 * p + 1][0], bf[2 * p + 1][1],
                                bK + kk * 32 + p * (16 * B_STRIDE));
#pragma unroll
                    for (int mt = 0; mt < 4; mt++)
#pragma unroll
                        for (int nt = 0; nt < 4; nt++)
                            mma_f16(acc[mt][nt][0], acc[mt][nt][1],
                                    acc[mt][nt][2], acc[mt][nt][3],
                                    af[mt][0], af[mt][1], af[mt][2], af[mt][3],
                                    bf[nt][0], bf[nt][1]);
                }

                if (ks == 7) {
                    const int n0 = nc * (NCODE / NQ) + (sc >> 3) * BN;
#pragma unroll
                    for (int nt = 0; nt < 4; nt++) {
                        int col = n0 + wn * 32 + nt * 8 + 2 * lk;
                        float cn0 = __ldg(&g_cnorm[col]);
                        float cn1 = __ldg(&g_cnorm[col + 1]);
#pragma unroll
                        for (int mt = 0; mt < 4; mt++) {
#pragma unroll
                            for (int h = 0; h < 2; h++) {
                                int bi = mt * 2 + h;
                                float d0 = fmaf(-2.f, acc[mt][nt][2 * h], cn0);
                                float d1 = fmaf(-2.f, acc[mt][nt][2 * h + 1], cn1);
                                if (d0 < bestd[bi]) { bestd[bi] = d0; besti[bi] = col; }
                                if (d1 < bestd[bi]) { bestd[bi] = d1; besti[bi] = col + 1; }
                            }
                        }
                    }
                }
            }
        }

        // ensure the pair finished reading the last buffers before the next
        // unit's B(0)/B(1) staging overwrites buffers 0,1
        PAIR_BAR(barid);

        // flush unit results: reduce over lk (4 lanes) then atomicMin
#pragma unroll
        for (int mt = 0; mt < 4; mt++)
#pragma unroll
            for (int h = 0; h < 2; h++) {
                int bi = mt * 2 + h;
                unsigned long long p =
                    ((unsigned long long)f2ord(bestd[bi]) << 32) | (unsigned int)besti[bi];
                p = min(p, __shfl_xor_sync(0xffffffffu, p, 1));
                p = min(p, __shfl_xor_sync(0xffffffffu, p, 2));
                if (lk == 0)
                    atomicMin(&g_best[m0 + wm * 64 + mt * 16 + h * 8 + lr], p);
            }
    }
}

// ---------------------------------------------------------------------------
__global__ void epilogue_kernel(const float* __restrict__ X,
                                const float* __restrict__ R,
                                const float* __restrict__ C,
                                float* __restrict__ out) {
    int warp = (blockIdx.x * blockDim.x + threadIdx.x) >> 5;
    int lane = threadIdx.x & 31;
    if (warp >= NTOK) return;

    int idx = (int)(g_best[warp] & 0xffffffffu);
    if (lane == 0) atomicAdd(&g_counts[idx], 1);

    const float4* xr = (const float4*)(X + (size_t)warp * DIM);
    const float4* rr = (const float4*)(R + (size_t)warp * DIM);
    const float4* cr = (const float4*)(C + (size_t)idx * DIM);

    float4 xs[2], rs[2];
    float r2 = 0.f, n2 = 0.f;
#pragma unroll
    for (int i = 0; i < 2; i++) {
        float4 x = xr[lane + 32 * i];
        float4 c = cr[lane + 32 * i];
        float4 r = rr[lane + 32 * i];
        xs[i] = x; rs[i] = r;
        float dx = x.x - c.x, dy = x.y - c.y, dz = x.z - c.z, dw = x.w - c.w;
        r2 += dx * dx + dy * dy + dz * dz + dw * dw;
        n2 += r.x * r.x + r.y * r.y + r.z * r.z + r.w * r.w;
    }
#pragma unroll
    for (int o = 16; o; o >>= 1) {
        r2 += __shfl_xor_sync(0xffffffffu, r2, o);
        n2 += __shfl_xor_sync(0xffffffffu, n2, o);
    }
    float scale = sqrtf(r2) / (sqrtf(n2) + EPSF);

    float4* orow = (float4*)(out + (size_t)warp * DIM);
#pragma unroll
    for (int i = 0; i < 2; i++) {
        float4 x = xs[i], r = rs[i], o4;
        o4.x = fmaf(scale, r.x, x.x);
        o4.y = fmaf(scale, r.y, x.y);
        o4.z = fmaf(scale, r.z, x.z);
        o4.w = fmaf(scale, r.w, x.w);
        orow[lane + 32 * i] = o4;
    }
}

// ---------------------------------------------------------------------------
__global__ void finalize_kernel(float* __restrict__ out, int out_size) {
    __shared__ float s_ent[32];
    __shared__ int   s_uni[32];
    int tid = threadIdx.x;

    float ent = 0.f;
    int   uni = 0;
    for (int i = tid; i < NCODE; i += blockDim.x) {
        int c = g_counts[i];
        if (c > 0) {
            uni++;
            float p = (float)c * (1.0f / (float)NTOK);
            ent += p * logf(p + EPSF);
        }
    }
#pragma unroll
    for (int o = 16; o; o >>= 1) {
        ent += __shfl_xor_sync(0xffffffffu, ent, o);
        uni += __shfl_xor_sync(0xffffffffu, uni, o);
    }
    int warp = tid >> 5, lane = tid & 31;
    if (lane == 0) { s_ent[warp] = ent; s_uni[warp] = uni; }
    __syncthreads();
    if (warp == 0) {
        int nw = (blockDim.x + 31) >> 5;
        ent = (lane < nw) ? s_ent[lane] : 0.f;
        uni = (lane < nw) ? s_uni[lane] : 0;
#pragma unroll
        for (int o = 16; o; o >>= 1) {
            ent += __shfl_xor_sync(0xffffffffu, ent, o);
            uni += __shfl_xor_sync(0xffffffffu, uni, o);
        }
        if (lane == 0) {
            long long base = (long long)NTOK * DIM;
            if (out_size > base)     out[base]     = expf(-ent);
            if (out_size > base + 1) out[base + 1] = (float)uni;
        }
    }
}

// ---------------------------------------------------------------------------
extern "C" void kernel_launch(void* const* d_in, const int* in_sizes, int n_in,
                              void* d_out, int out_size) {
    const float* X = (const float*)d_in[0];
    const float* R = (const float*)d_in[1];
    const float* C = (const float*)d_in[2];
    float* out = (float*)d_out;

    cudaFuncSetAttribute(argmin_mma_kernel,
                         cudaFuncAttributeMaxDynamicSharedMemorySize, SM_TOTAL);

    prep_kernel<<<NCODE / 8, 256>>>(C);
    argmin_mma_kernel<<<GRID, THREADS, SM_TOTAL>>>(X);
    epilogue_kernel<<<(NTOK * 32) / 256, 256>>>(X, R, C, out);
    finalize_kernel<<<1, 1024>>>(out, out_size);
}